// round 1
// baseline (speedup 1.0000x reference)
#include <cuda_runtime.h>
#include <cstdio>

#define B_   2
#define A_   512
#define T_   512
#define F_   128
#define RBF_ 25
#define RS   28    // sR row stride (floats)
#define HS   132   // sH1 row stride (floats, multiple of 4)

#define NCHUNK (T_/16)

// Precomputed y = x @ Win, [B,A,F]
__device__ __align__(16) float g_y[B_ * A_ * F_];

__device__ __forceinline__ float ssp(float v) {
    // softplus(v) - log(2), numerically stable
    return fmaxf(v, 0.0f) + log1pf(__expf(-fabsf(v))) - 0.69314718055994530942f;
}

// ---------------------------------------------------------------------------
// Kernel 1: y[ba,f] = sum_i x[ba,i] * Win[i,f]
// ---------------------------------------------------------------------------
__global__ __launch_bounds__(128) void y_kernel(const float* __restrict__ x,
                                                const float* __restrict__ Win) {
    int ba = blockIdx.x;
    int f  = threadIdx.x;
    __shared__ float xs[F_];
    xs[f] = x[ba * F_ + f];
    __syncthreads();
    float acc = 0.0f;
#pragma unroll 8
    for (int i = 0; i < F_; i++) {
        acc = fmaf(xs[i], Win[i * F_ + f], acc);
    }
    g_y[ba * F_ + f] = acc;
}

// ---------------------------------------------------------------------------
// Kernel 2: fully fused CFConv-angular per (b,a) tile.
// 128 threads: q = tid%32 -> feature quad (f = 4q..4q+3)
//              tg = tid/32 -> triplet sub-group (4 t's per chunk of 16)
// ---------------------------------------------------------------------------
__global__ __launch_bounds__(128, 2) void cfconv_kernel(
    const float* __restrict__ r_ij,
    const float* __restrict__ mask,
    const float* __restrict__ Wf1,
    const float* __restrict__ bf1,
    const float* __restrict__ Wf2,
    const float* __restrict__ bf2,
    const float* __restrict__ Wout,
    const float* __restrict__ bout,
    const int*   __restrict__ nbr_j,
    const int*   __restrict__ nbr_k,
    float*       __restrict__ out)
{
    extern __shared__ float smem[];
    float* sWf2 = smem;                 // 128*128 = 16384
    float* sWf1 = sWf2 + F_ * F_;       // 25*128  = 3200
    float* sbf1 = sWf1 + RBF_ * F_;     // 128
    float* sbf2 = sbf1 + F_;            // 128
    float* sR   = sbf2 + F_;            // 16*28   = 448
    float* sH1  = sR + 16 * RS;         // 16*132  = 2112
    float* sRed = sH1 + 16 * HS;        // 4*128   = 512
    float* sAcc = sRed + 4 * F_;        // 128

    const int tid = threadIdx.x;
    const int q   = tid & 31;   // feature quad
    const int tg  = tid >> 5;   // triplet group (== warp id)
    const int ba  = blockIdx.x;
    const int b   = ba / A_;

    // Load weights into shared (L2-hot after first blocks)
    for (int i = tid; i < F_ * F_; i += 128) sWf2[i] = Wf2[i];
    for (int i = tid; i < RBF_ * F_; i += 128) sWf1[i] = Wf1[i];
    sbf1[tid] = bf1[tid];
    sbf2[tid] = bf2[tid];

    const float4* w1v = (const float4*)sWf1;
    const float4* w2v = (const float4*)sWf2;
    const float4* yv  = (const float4*)g_y;

    float4 facc = make_float4(0.f, 0.f, 0.f, 0.f);

    for (int c = 0; c < NCHUNK; c++) {
        const int t0 = c * 16;

        // cooperative load of r_ij chunk [16, 25]
        for (int i = tid; i < 16 * RBF_; i += 128) {
            int t = i / RBF_;
            int r = i - t * RBF_;
            sR[t * RS + r] = r_ij[(size_t)(ba * T_ + t0 + t) * RBF_ + r];
        }
        __syncthreads();   // also guarantees prev chunk fully consumed

        // ---- stage 1: H1 = ssp(r @ Wf1 + bf1), 4t x 4f micro-tile ----
        float a1[4][4];
#pragma unroll
        for (int tt = 0; tt < 4; tt++)
#pragma unroll
            for (int j = 0; j < 4; j++) a1[tt][j] = 0.0f;

#pragma unroll
        for (int r = 0; r < RBF_; r++) {
            float4 w = w1v[r * 32 + q];
#pragma unroll
            for (int tt = 0; tt < 4; tt++) {
                float rv = sR[(tg * 4 + tt) * RS + r];
                a1[tt][0] = fmaf(rv, w.x, a1[tt][0]);
                a1[tt][1] = fmaf(rv, w.y, a1[tt][1]);
                a1[tt][2] = fmaf(rv, w.z, a1[tt][2]);
                a1[tt][3] = fmaf(rv, w.w, a1[tt][3]);
            }
        }
        {
            float4 b1 = ((const float4*)sbf1)[q];
#pragma unroll
            for (int tt = 0; tt < 4; tt++) {
                float4 h;
                h.x = ssp(a1[tt][0] + b1.x);
                h.y = ssp(a1[tt][1] + b1.y);
                h.z = ssp(a1[tt][2] + b1.z);
                h.w = ssp(a1[tt][3] + b1.w);
                ((float4*)(sH1 + (tg * 4 + tt) * HS))[q] = h;
            }
        }
        __syncthreads();

        // ---- stage 2: W = H1 @ Wf2 (+bf2), same micro-tile ----
        float a2[4][4];
#pragma unroll
        for (int tt = 0; tt < 4; tt++)
#pragma unroll
            for (int j = 0; j < 4; j++) a2[tt][j] = 0.0f;

#pragma unroll 4
        for (int g = 0; g < F_; g++) {
            float4 w = w2v[g * 32 + q];
#pragma unroll
            for (int tt = 0; tt < 4; tt++) {
                float h = sH1[(tg * 4 + tt) * HS + g];
                a2[tt][0] = fmaf(h, w.x, a2[tt][0]);
                a2[tt][1] = fmaf(h, w.y, a2[tt][1]);
                a2[tt][2] = fmaf(h, w.z, a2[tt][2]);
                a2[tt][3] = fmaf(h, w.w, a2[tt][3]);
            }
        }

        // ---- gather y_j, y_k + triple product + accumulate over t ----
        {
            float4 b2 = ((const float4*)sbf2)[q];
#pragma unroll
            for (int tt = 0; tt < 4; tt++) {
                int gt = ba * T_ + t0 + tg * 4 + tt;
                float m = mask[gt];
                int nj  = nbr_j[gt];
                int nk  = nbr_k[gt];
                float4 yj = yv[(b * A_ + nj) * 32 + q];
                float4 yk = yv[(b * A_ + nk) * 32 + q];
                float w0 = a2[tt][0] + b2.x;
                float w1 = a2[tt][1] + b2.y;
                float w2 = a2[tt][2] + b2.z;
                float w3 = a2[tt][3] + b2.w;
                facc.x = fmaf(yj.x * yk.x * m, w0, facc.x);
                facc.y = fmaf(yj.y * yk.y * m, w1, facc.y);
                facc.z = fmaf(yj.z * yk.z * m, w2, facc.z);
                facc.w = fmaf(yj.w * yk.w * m, w3, facc.w);
            }
        }
        // no sync here: next iteration's load-sync provides the barrier
    }

    // ---- reduce over the 4 t-groups ----
    ((float4*)(sRed + tg * F_))[q] = facc;
    __syncthreads();
    {
        float a = sRed[0 * F_ + tid] + sRed[1 * F_ + tid] +
                  sRed[2 * F_ + tid] + sRed[3 * F_ + tid];
        sAcc[tid] = a;
    }
    __syncthreads();

    // ---- f2out: out = ssp(acc @ Wout + bout) ----
    {
        float o = bout[tid];
#pragma unroll 8
        for (int g = 0; g < F_; g++) {
            o = fmaf(sAcc[g], Wout[g * F_ + tid], o);
        }
        out[ba * F_ + tid] = ssp(o);
    }
}

// ---------------------------------------------------------------------------
// Launch
// ---------------------------------------------------------------------------
extern "C" void kernel_launch(void* const* d_in, const int* in_sizes, int n_in,
                              void* d_out, int out_size)
{
    const float* x     = (const float*)d_in[0];
    const float* r_ij  = (const float*)d_in[1];
    const float* mask  = (const float*)d_in[2];
    const float* Wf1   = (const float*)d_in[3];
    const float* bf1   = (const float*)d_in[4];
    const float* Wf2   = (const float*)d_in[5];
    const float* bf2   = (const float*)d_in[6];
    const float* Win   = (const float*)d_in[7];
    const float* Wout  = (const float*)d_in[8];
    const float* bout  = (const float*)d_in[9];
    const int*   nbr_j = (const int*)d_in[10];
    const int*   nbr_k = (const int*)d_in[11];
    float* out = (float*)d_out;

    const int smem_bytes =
        (F_ * F_ + RBF_ * F_ + F_ + F_ + 16 * RS + 16 * HS + 4 * F_ + F_) * 4;

    cudaFuncSetAttribute(cfconv_kernel,
                         cudaFuncAttributeMaxDynamicSharedMemorySize, smem_bytes);

    y_kernel<<<B_ * A_, 128>>>(x, Win);
    cfconv_kernel<<<B_ * A_, 128, smem_bytes>>>(
        r_ij, mask, Wf1, bf1, Wf2, bf2, Wout, bout, nbr_j, nbr_k, out);
}

// round 3
// speedup vs baseline: 2.2450x; 2.2450x over previous
#include <cuda_runtime.h>
#include <cstdint>

#define B_   2
#define A_   512
#define T_   512
#define F_   128
#define RBF_ 25
#define TBLK 128
#define NBLK (T_/TBLK)

// Precomputed y = x @ Win, [B,A,F]
__device__ __align__(16) float g_y[B_ * A_ * F_];

// ---------------- smem layout (float offsets) ----------------
#define OFF_WF1 0               // [32][136] tf32      4352
#define OFF_RS  4352            // [128][36] tf32      4608
#define OFF_H1  8960            // [128][136] tf32     17408
#define OFF_GT  26368           // [128][136] tf32     17408  (reused: Wf2 [128][128])
#define OFF_BF1 43776           // 128
#define OFF_NJ  43904           // 128 int
#define OFF_NK  44032           // 128 int
#define OFF_MSK 44160           // 128
#define OFF_GS  44288           // 128
#define OFF_PRT 44416           // 256
#define OFF_ACC 44672           // 128
#define SMEM_FLOATS 44800
#define SMEM_BYTES  (SMEM_FLOATS * 4)

static __device__ __forceinline__ float ssp(float v) {
    return fmaxf(v, 0.0f) + log1pf(__expf(-fabsf(v))) - 0.69314718055994530942f;
}
static __device__ __forceinline__ uint32_t f2t(float f) {
    uint32_t r;
    asm("cvt.rna.tf32.f32 %0, %1;" : "=r"(r) : "f"(f));
    return r;
}
static __device__ __forceinline__ void mma8(float* d, const uint32_t* a,
                                            const uint32_t* b) {
    asm volatile(
        "mma.sync.aligned.m16n8k8.row.col.f32.tf32.tf32.f32 "
        "{%0,%1,%2,%3}, {%4,%5,%6,%7}, {%8,%9}, {%0,%1,%2,%3};"
        : "+f"(d[0]), "+f"(d[1]), "+f"(d[2]), "+f"(d[3])
        : "r"(a[0]), "r"(a[1]), "r"(a[2]), "r"(a[3]),
          "r"(b[0]), "r"(b[1]));
}

// ---------------------------------------------------------------------------
// Kernel 1: y[ba,f] = sum_i x[ba,i] * Win[i,f]
// ---------------------------------------------------------------------------
__global__ __launch_bounds__(128) void y_kernel(const float* __restrict__ x,
                                                const float* __restrict__ Win) {
    int ba = blockIdx.x, f = threadIdx.x;
    __shared__ float xs[F_];
    xs[f] = x[ba * F_ + f];
    __syncthreads();
    float acc = 0.0f;
#pragma unroll 8
    for (int i = 0; i < F_; i++) acc = fmaf(xs[i], Win[i * F_ + f], acc);
    g_y[ba * F_ + f] = acc;
}

// ---------------------------------------------------------------------------
// Main fused kernel. One CTA per (b,a). 256 threads = 8 warps.
// Per block of 128 triplets:
//   wg0 (warps 0-3): load R, stage-1 MMA H1 = ssp(R @ Wf1 + bf1) -> sH1 (tf32)
//   wg1 (warps 4-7): gather G = yj*yk*mask -> sGT (tf32), accumulate gsum
//   all 8 warps:     stage-2 MMA  P[f,g] += G^T @ H1   (register accumulator)
// Epilogue: out = ssp( (P .dot_g Wf2[g,f]) + bf2*gsum  -> @Wout + bout )
// ---------------------------------------------------------------------------
__global__ __launch_bounds__(256, 1) void cfconv_mma(
    const float* __restrict__ r_ij,
    const float* __restrict__ mask,
    const float* __restrict__ Wf1,
    const float* __restrict__ bf1,
    const float* __restrict__ Wf2,
    const float* __restrict__ bf2,
    const float* __restrict__ Wout,
    const float* __restrict__ bout,
    const int*   __restrict__ nbr_j,
    const int*   __restrict__ nbr_k,
    float*       __restrict__ out)
{
    extern __shared__ float sm[];
    uint32_t* smu = (uint32_t*)sm;

    const int tid  = threadIdx.x;
    const int wid  = tid >> 5;
    const int lane = tid & 31;
    const int gr   = lane >> 2;     // groupID
    const int t4   = lane & 3;      // threadInGroup
    const int ba   = blockIdx.x;
    const int b    = ba / A_;

    // ---- one-time loads ----
    // Wf1s[k][g], K padded 25->32 with zeros, tf32
    for (int i = tid; i < 32 * F_; i += 256) {
        int k = i >> 7, g = i & 127;
        float v = (k < RBF_) ? Wf1[k * F_ + g] : 0.0f;
        smu[OFF_WF1 + k * 136 + g] = f2t(v);
    }
    if (tid < 128) sm[OFF_BF1 + tid] = bf1[tid];
    __syncthreads();

    // persistent accumulator P: warp (wm, wn) owns f-rows [wm*32,wm*32+32),
    // g-cols [wn*64, wn*64+64); per-thread 2 mtiles x 8 ntiles x 4
    const int wm = wid & 3, wn = wid >> 2;
    const int m0 = wm * 32, n0 = wn * 64;
    float P[2][8][4];
#pragma unroll
    for (int mt = 0; mt < 2; mt++)
#pragma unroll
        for (int nt = 0; nt < 8; nt++)
#pragma unroll
            for (int j = 0; j < 4; j++) P[mt][nt][j] = 0.0f;

    float gsum = 0.0f;  // wg1 only

    for (int blk = 0; blk < NBLK; blk++) {
        const int t0g = ba * T_ + blk * TBLK;

        if (tid < 128) {
            // ===== wg0: load R block [128t][32r] tf32 =====
            for (int i = tid; i < TBLK * 32; i += 128) {
                int t = i >> 5, r = i & 31;
                float v = (r < RBF_)
                        ? r_ij[(size_t)(t0g + t) * RBF_ + r] : 0.0f;
                smu[OFF_RS + t * 36 + r] = f2t(v);
            }
            asm volatile("bar.sync 1, 128;" ::: "memory");

            // ===== stage 1: H1 = ssp(R @ Wf1 + bf1) =====
            const int tb = wid * 32;     // wid 0..3
#pragma unroll
            for (int half = 0; half < 2; half++) {
                const int nb = half * 64;
                float s1[2][8][4];
#pragma unroll
                for (int mt = 0; mt < 2; mt++)
#pragma unroll
                    for (int nt = 0; nt < 8; nt++)
#pragma unroll
                        for (int j = 0; j < 4; j++) s1[mt][nt][j] = 0.0f;

#pragma unroll
                for (int k = 0; k < 4; k++) {
                    const int kk = k * 8;
                    uint32_t a[2][4];
#pragma unroll
                    for (int mt = 0; mt < 2; mt++) {
                        int r0 = tb + mt * 16 + gr;
                        a[mt][0] = smu[OFF_RS + r0 * 36 + kk + t4];
                        a[mt][1] = smu[OFF_RS + (r0 + 8) * 36 + kk + t4];
                        a[mt][2] = smu[OFF_RS + r0 * 36 + kk + t4 + 4];
                        a[mt][3] = smu[OFF_RS + (r0 + 8) * 36 + kk + t4 + 4];
                    }
#pragma unroll
                    for (int nt = 0; nt < 8; nt++) {
                        uint32_t bfr[2];
                        int c = nb + nt * 8 + gr;
                        bfr[0] = smu[OFF_WF1 + (kk + t4) * 136 + c];
                        bfr[1] = smu[OFF_WF1 + (kk + t4 + 4) * 136 + c];
                        mma8(s1[0][nt], a[0], bfr);
                        mma8(s1[1][nt], a[1], bfr);
                    }
                }
                // bias + ssp + store tf32 to sH1[t][g]
#pragma unroll
                for (int nt = 0; nt < 8; nt++) {
                    int c = nb + nt * 8 + 2 * t4;
                    float bc0 = sm[OFF_BF1 + c];
                    float bc1 = sm[OFF_BF1 + c + 1];
#pragma unroll
                    for (int mt = 0; mt < 2; mt++) {
                        int r0 = tb + mt * 16 + gr;
                        smu[OFF_H1 + r0 * 136 + c]     = f2t(ssp(s1[mt][nt][0] + bc0));
                        smu[OFF_H1 + r0 * 136 + c + 1] = f2t(ssp(s1[mt][nt][1] + bc1));
                        smu[OFF_H1 + (r0 + 8) * 136 + c]     = f2t(ssp(s1[mt][nt][2] + bc0));
                        smu[OFF_H1 + (r0 + 8) * 136 + c + 1] = f2t(ssp(s1[mt][nt][3] + bc1));
                    }
                }
            }
        } else {
            // ===== wg1: gather G^T[f][t] =====
            const int f = tid - 128;
            ((int*)(sm + OFF_NJ))[f] = nbr_j[t0g + f];
            ((int*)(sm + OFF_NK))[f] = nbr_k[t0g + f];
            sm[OFF_MSK + f]          = mask[t0g + f];
            asm volatile("bar.sync 2, 128;" ::: "memory");

            const float* yb  = g_y + (size_t)b * A_ * F_;
            const int*   sNj = (const int*)(sm + OFF_NJ);
            const int*   sNk = (const int*)(sm + OFF_NK);
            const float* sM  = sm + OFF_MSK;

            for (int tt = 0; tt < TBLK; tt += 4) {
                uint4 gq;
                uint32_t* gp = (uint32_t*)&gq;
#pragma unroll
                for (int w = 0; w < 4; w++) {
                    int t = tt + w;
                    float gv = yb[(size_t)sNj[t] * F_ + f]
                             * yb[(size_t)sNk[t] * F_ + f] * sM[t];
                    gsum += gv;
                    gp[w] = f2t(gv);
                }
                *(uint4*)&smu[OFF_GT + f * 136 + tt] = gq;
            }
        }
        __syncthreads();

        // ===== stage 2: P[f][g] += G^T @ H1  (K = 128) =====
#pragma unroll 4
        for (int k = 0; k < 16; k++) {
            const int kk = k * 8;
            uint32_t a[2][4];
#pragma unroll
            for (int mt = 0; mt < 2; mt++) {
                int r0 = m0 + mt * 16 + gr;
                a[mt][0] = smu[OFF_GT + r0 * 136 + kk + t4];
                a[mt][1] = smu[OFF_GT + (r0 + 8) * 136 + kk + t4];
                a[mt][2] = smu[OFF_GT + r0 * 136 + kk + t4 + 4];
                a[mt][3] = smu[OFF_GT + (r0 + 8) * 136 + kk + t4 + 4];
            }
#pragma unroll
            for (int nt = 0; nt < 8; nt++) {
                uint32_t bfr[2];
                int c = n0 + nt * 8 + gr;
                bfr[0] = smu[OFF_H1 + (kk + t4) * 136 + c];
                bfr[1] = smu[OFF_H1 + (kk + t4 + 4) * 136 + c];
                mma8(P[0][nt], a[0], bfr);
                mma8(P[1][nt], a[1], bfr);
            }
        }
        __syncthreads();
    }

    // ---- epilogue ----
    if (tid >= 128) sm[OFF_GS + tid - 128] = gsum;
    // Wf2[g][f] into the GT region (plain fp32)
    for (int i = tid; i < F_ * F_; i += 256) sm[OFF_GT + i] = Wf2[i];
    __syncthreads();

    // per-warp: partial[f] = sum over this warp's g-cols of P[f][g]*Wf2[g][f]
#pragma unroll
    for (int mt = 0; mt < 2; mt++) {
        int f0 = m0 + mt * 16 + gr;
        int f1 = f0 + 8;
        float p0 = 0.0f, p1 = 0.0f;
#pragma unroll
        for (int nt = 0; nt < 8; nt++) {
            int c = n0 + nt * 8 + 2 * t4;
            p0 += P[mt][nt][0] * sm[OFF_GT + c * F_ + f0]
                + P[mt][nt][1] * sm[OFF_GT + (c + 1) * F_ + f0];
            p1 += P[mt][nt][2] * sm[OFF_GT + c * F_ + f1]
                + P[mt][nt][3] * sm[OFF_GT + (c + 1) * F_ + f1];
        }
        p0 += __shfl_xor_sync(0xFFFFFFFFu, p0, 1);
        p0 += __shfl_xor_sync(0xFFFFFFFFu, p0, 2);
        p1 += __shfl_xor_sync(0xFFFFFFFFu, p1, 1);
        p1 += __shfl_xor_sync(0xFFFFFFFFu, p1, 2);
        if (t4 == 0) {
            sm[OFF_PRT + wn * F_ + f0] = p0;
            sm[OFF_PRT + wn * F_ + f1] = p1;
        }
    }
    __syncthreads();

    if (tid < 128) {
        float acc = sm[OFF_PRT + tid] + sm[OFF_PRT + F_ + tid]
                  + bf2[tid] * sm[OFF_GS + tid];
        sm[OFF_ACC + tid] = acc;
    }
    __syncthreads();

    if (tid < 128) {
        float o = bout[tid];
#pragma unroll 8
        for (int g = 0; g < F_; g++)
            o = fmaf(sm[OFF_ACC + g], Wout[g * F_ + tid], o);
        out[(size_t)ba * F_ + tid] = ssp(o);
    }
}

// ---------------------------------------------------------------------------
extern "C" void kernel_launch(void* const* d_in, const int* in_sizes, int n_in,
                              void* d_out, int out_size)
{
    const float* x     = (const float*)d_in[0];
    const float* r_ij  = (const float*)d_in[1];
    const float* mask  = (const float*)d_in[2];
    const float* Wf1   = (const float*)d_in[3];
    const float* bf1   = (const float*)d_in[4];
    const float* Wf2   = (const float*)d_in[5];
    const float* bf2   = (const float*)d_in[6];
    const float* Win   = (const float*)d_in[7];
    const float* Wout  = (const float*)d_in[8];
    const float* bout  = (const float*)d_in[9];
    const int*   nbr_j = (const int*)d_in[10];
    const int*   nbr_k = (const int*)d_in[11];
    float* out = (float*)d_out;

    cudaFuncSetAttribute(cfconv_mma,
                         cudaFuncAttributeMaxDynamicSharedMemorySize,
                         SMEM_BYTES);

    y_kernel<<<B_ * A_, 128>>>(x, Win);
    cfconv_mma<<<B_ * A_, 256, SMEM_BYTES>>>(
        r_ij, mask, Wf1, bf1, Wf2, bf2, Wout, bout, nbr_j, nbr_k, out);
}

// round 4
// speedup vs baseline: 2.8475x; 1.2684x over previous
#include <cuda_runtime.h>
#include <cstdint>

#define B_   2
#define A_   512
#define T_   512
#define F_   128
#define RBF_ 25
#define TBLK 128
#define NBLK (T_/TBLK)

// Precomputed y = x @ Win, [B,A,F]
__device__ __align__(16) float g_y[B_ * A_ * F_];

// ---------------- smem layout (float offsets) ----------------
#define OFF_WF1 0               // [32][136] tf32      4352
#define OFF_RS  4352            // [128][36] tf32      4608
#define OFF_H1  8960            // [128][136] tf32     17408 (stride 136: B-frag conflict-free)
#define OFF_GT  26368           // [128][132] tf32     16896 (stride 132: A-frag conflict-free; reused: Wf2 [128][128])
#define OFF_BF1 43264           // 128
#define OFF_NJ  43392           // 128 int
#define OFF_NK  43520           // 128 int
#define OFF_MSK 43648           // 128
#define OFF_GS  43776           // 256 (two t-half partials)
#define OFF_PRT 44032           // 4*128
#define OFF_ACC 44544           // 128
#define SMEM_FLOATS 44672
#define SMEM_BYTES  (SMEM_FLOATS * 4)

static __device__ __forceinline__ float ssp(float v) {
    return fmaxf(v, 0.0f) + log1pf(__expf(-fabsf(v))) - 0.69314718055994530942f;
}
static __device__ __forceinline__ uint32_t f2t(float f) {
    uint32_t r;
    asm("cvt.rna.tf32.f32 %0, %1;" : "=r"(r) : "f"(f));
    return r;
}
static __device__ __forceinline__ void mma8(float* d, const uint32_t* a,
                                            const uint32_t* b) {
    asm volatile(
        "mma.sync.aligned.m16n8k8.row.col.f32.tf32.tf32.f32 "
        "{%0,%1,%2,%3}, {%4,%5,%6,%7}, {%8,%9}, {%0,%1,%2,%3};"
        : "+f"(d[0]), "+f"(d[1]), "+f"(d[2]), "+f"(d[3])
        : "r"(a[0]), "r"(a[1]), "r"(a[2]), "r"(a[3]),
          "r"(b[0]), "r"(b[1]));
}

// ---------------------------------------------------------------------------
// Kernel 1: y[ba,f] = sum_i x[ba,i] * Win[i,f]
// ---------------------------------------------------------------------------
__global__ __launch_bounds__(128) void y_kernel(const float* __restrict__ x,
                                                const float* __restrict__ Win) {
    int ba = blockIdx.x, f = threadIdx.x;
    __shared__ float xs[F_];
    xs[f] = x[ba * F_ + f];
    __syncthreads();
    float acc = 0.0f;
#pragma unroll 8
    for (int i = 0; i < F_; i++) acc = fmaf(xs[i], Win[i * F_ + f], acc);
    g_y[ba * F_ + f] = acc;
}

// ---------------------------------------------------------------------------
// Main fused kernel. One CTA per (b,a). 512 threads = 16 warps.
// Per block of 128 triplets:
//   warps 0-7:  load R, stage-1 MMA H1 = ssp(R @ Wf1 + bf1) -> sH1 (tf32)
//   warps 8-15: gather G = yj*yk*mask -> sGT (tf32), gsum partials
//   all 16:     stage-2 MMA  P[f,g] += G^T @ H1  (32x32 reg tile per warp)
// Epilogue: out = ssp( (P .dot_g Wf2[g,f]) + bf2*gsum  -> @Wout + bout )
// ---------------------------------------------------------------------------
__global__ __launch_bounds__(512, 1) void cfconv_mma(
    const float* __restrict__ r_ij,
    const float* __restrict__ mask,
    const float* __restrict__ Wf1,
    const float* __restrict__ bf1,
    const float* __restrict__ Wf2,
    const float* __restrict__ bf2,
    const float* __restrict__ Wout,
    const float* __restrict__ bout,
    const int*   __restrict__ nbr_j,
    const int*   __restrict__ nbr_k,
    float*       __restrict__ out)
{
    extern __shared__ float sm[];
    uint32_t* smu = (uint32_t*)sm;

    const int tid  = threadIdx.x;
    const int wid  = tid >> 5;
    const int lane = tid & 31;
    const int gr   = lane >> 2;     // groupID
    const int t4   = lane & 3;      // threadInGroup
    const int ba   = blockIdx.x;
    const int b    = ba / A_;

    // ---- one-time loads ----
    for (int i = tid; i < 32 * F_; i += 512) {
        int k = i >> 7, g = i & 127;
        float v = (k < RBF_) ? Wf1[k * F_ + g] : 0.0f;
        smu[OFF_WF1 + k * 136 + g] = f2t(v);
    }
    if (tid < 128) sm[OFF_BF1 + tid] = bf1[tid];
    __syncthreads();

    // stage-2 accumulator: warp (wm,wn) owns f-rows [wm*32,+32), g-cols [wn*32,+32)
    const int wm = wid & 3, wn = wid >> 2;
    const int m0 = wm * 32, n0 = wn * 32;
    float P[2][4][4];
#pragma unroll
    for (int mt = 0; mt < 2; mt++)
#pragma unroll
        for (int nt = 0; nt < 4; nt++)
#pragma unroll
            for (int j = 0; j < 4; j++) P[mt][nt][j] = 0.0f;

    float gsum = 0.0f;  // gather threads only

    for (int blk = 0; blk < NBLK; blk++) {
        const int t0g = ba * T_ + blk * TBLK;

        if (tid < 256) {
            // ===== warps 0-7: load R block [128t][32r] tf32 =====
            for (int i = tid; i < TBLK * 32; i += 256) {
                int t = i >> 5, r = i & 31;
                float v = (r < RBF_)
                        ? r_ij[(size_t)(t0g + t) * RBF_ + r] : 0.0f;
                smu[OFF_RS + t * 36 + r] = f2t(v);
            }
            asm volatile("bar.sync 1, 256;" ::: "memory");

            // ===== stage 1: H1 = ssp(R @ Wf1 + bf1), one 16-row mtile/warp =====
            const int tb = wid * 16;
#pragma unroll
            for (int half = 0; half < 2; half++) {
                const int nb = half * 64;
                float s1[8][4];
#pragma unroll
                for (int nt = 0; nt < 8; nt++)
#pragma unroll
                    for (int j = 0; j < 4; j++) s1[nt][j] = 0.0f;

#pragma unroll
                for (int k = 0; k < 4; k++) {
                    const int kk = k * 8;
                    uint32_t a[4];
                    a[0] = smu[OFF_RS + (tb + gr) * 36 + kk + t4];
                    a[1] = smu[OFF_RS + (tb + gr + 8) * 36 + kk + t4];
                    a[2] = smu[OFF_RS + (tb + gr) * 36 + kk + t4 + 4];
                    a[3] = smu[OFF_RS + (tb + gr + 8) * 36 + kk + t4 + 4];
#pragma unroll
                    for (int nt = 0; nt < 8; nt++) {
                        uint32_t bfr[2];
                        int c = nb + nt * 8 + gr;
                        bfr[0] = smu[OFF_WF1 + (kk + t4) * 136 + c];
                        bfr[1] = smu[OFF_WF1 + (kk + t4 + 4) * 136 + c];
                        mma8(s1[nt], a, bfr);
                    }
                }
#pragma unroll
                for (int nt = 0; nt < 8; nt++) {
                    int c = nb + nt * 8 + 2 * t4;
                    float bc0 = sm[OFF_BF1 + c];
                    float bc1 = sm[OFF_BF1 + c + 1];
                    smu[OFF_H1 + (tb + gr) * 136 + c]     = f2t(ssp(s1[nt][0] + bc0));
                    smu[OFF_H1 + (tb + gr) * 136 + c + 1] = f2t(ssp(s1[nt][1] + bc1));
                    smu[OFF_H1 + (tb + gr + 8) * 136 + c]     = f2t(ssp(s1[nt][2] + bc0));
                    smu[OFF_H1 + (tb + gr + 8) * 136 + c + 1] = f2t(ssp(s1[nt][3] + bc1));
                }
            }
        } else {
            // ===== warps 8-15: gather G^T[f][t], t split in halves =====
            const int idx = tid - 256;
            const int f   = idx & 127;
            const int th  = idx >> 7;        // 0 or 1
            if (idx < 128) {
                ((int*)(sm + OFF_NJ))[idx] = nbr_j[t0g + idx];
                ((int*)(sm + OFF_NK))[idx] = nbr_k[t0g + idx];
                sm[OFF_MSK + idx]          = mask[t0g + idx];
            }
            asm volatile("bar.sync 2, 256;" ::: "memory");

            const float* yb  = g_y + (size_t)b * A_ * F_;
            const int*   sNj = (const int*)(sm + OFF_NJ);
            const int*   sNk = (const int*)(sm + OFF_NK);
            const float* sM  = sm + OFF_MSK;

            const int tbeg = th * 64;
            for (int tt = tbeg; tt < tbeg + 64; tt += 4) {
                uint4 gq;
                uint32_t* gp = (uint32_t*)&gq;
#pragma unroll
                for (int w = 0; w < 4; w++) {
                    int t = tt + w;
                    float gv = yb[(size_t)sNj[t] * F_ + f]
                             * yb[(size_t)sNk[t] * F_ + f] * sM[t];
                    gsum += gv;
                    gp[w] = f2t(gv);
                }
                *(uint4*)&smu[OFF_GT + f * 132 + tt] = gq;
            }
        }
        __syncthreads();

        // ===== stage 2: P += G^T @ H1  (K = 128), all 16 warps =====
#pragma unroll 4
        for (int k = 0; k < 16; k++) {
            const int kk = k * 8;
            uint32_t a[2][4];
#pragma unroll
            for (int mt = 0; mt < 2; mt++) {
                int r0 = m0 + mt * 16 + gr;
                a[mt][0] = smu[OFF_GT + r0 * 132 + kk + t4];
                a[mt][1] = smu[OFF_GT + (r0 + 8) * 132 + kk + t4];
                a[mt][2] = smu[OFF_GT + r0 * 132 + kk + t4 + 4];
                a[mt][3] = smu[OFF_GT + (r0 + 8) * 132 + kk + t4 + 4];
            }
#pragma unroll
            for (int nt = 0; nt < 4; nt++) {
                uint32_t bfr[2];
                int c = n0 + nt * 8 + gr;
                bfr[0] = smu[OFF_H1 + (kk + t4) * 136 + c];
                bfr[1] = smu[OFF_H1 + (kk + t4 + 4) * 136 + c];
                mma8(P[0][nt], a[0], bfr);
                mma8(P[1][nt], a[1], bfr);
            }
        }
        __syncthreads();
    }

    // ---- epilogue ----
    if (tid >= 256) sm[OFF_GS + tid - 256] = gsum;
    // Wf2[g][f] into the GT region (plain fp32)
    for (int i = tid; i < F_ * F_; i += 512) sm[OFF_GT + i] = Wf2[i];
    __syncthreads();

    // per-warp: partial[f] = sum over this warp's 32 g-cols of P[f][g]*Wf2[g][f]
#pragma unroll
    for (int mt = 0; mt < 2; mt++) {
        int f0 = m0 + mt * 16 + gr;
        int f1 = f0 + 8;
        float p0 = 0.0f, p1 = 0.0f;
#pragma unroll
        for (int nt = 0; nt < 4; nt++) {
            int c = n0 + nt * 8 + 2 * t4;
            p0 += P[mt][nt][0] * sm[OFF_GT + c * F_ + f0]
                + P[mt][nt][1] * sm[OFF_GT + (c + 1) * F_ + f0];
            p1 += P[mt][nt][2] * sm[OFF_GT + c * F_ + f1]
                + P[mt][nt][3] * sm[OFF_GT + (c + 1) * F_ + f1];
        }
        p0 += __shfl_xor_sync(0xFFFFFFFFu, p0, 1);
        p0 += __shfl_xor_sync(0xFFFFFFFFu, p0, 2);
        p1 += __shfl_xor_sync(0xFFFFFFFFu, p1, 1);
        p1 += __shfl_xor_sync(0xFFFFFFFFu, p1, 2);
        if (t4 == 0) {
            sm[OFF_PRT + wn * F_ + f0] = p0;
            sm[OFF_PRT + wn * F_ + f1] = p1;
        }
    }
    __syncthreads();

    if (tid < 128) {
        float acc = sm[OFF_PRT + tid]          + sm[OFF_PRT + F_ + tid]
                  + sm[OFF_PRT + 2 * F_ + tid] + sm[OFF_PRT + 3 * F_ + tid]
                  + bf2[tid] * (sm[OFF_GS + tid] + sm[OFF_GS + tid + 128]);
        sm[OFF_ACC + tid] = acc;
    }
    __syncthreads();

    if (tid < 128) {
        float o = bout[tid];
#pragma unroll 8
        for (int g = 0; g < F_; g++)
            o = fmaf(sm[OFF_ACC + g], Wout[g * F_ + tid], o);
        out[(size_t)ba * F_ + tid] = ssp(o);
    }
}

// ---------------------------------------------------------------------------
extern "C" void kernel_launch(void* const* d_in, const int* in_sizes, int n_in,
                              void* d_out, int out_size)
{
    const float* x     = (const float*)d_in[0];
    const float* r_ij  = (const float*)d_in[1];
    const float* mask  = (const float*)d_in[2];
    const float* Wf1   = (const float*)d_in[3];
    const float* bf1   = (const float*)d_in[4];
    const float* Wf2   = (const float*)d_in[5];
    const float* bf2   = (const float*)d_in[6];
    const float* Win   = (const float*)d_in[7];
    const float* Wout  = (const float*)d_in[8];
    const float* bout  = (const float*)d_in[9];
    const int*   nbr_j = (const int*)d_in[10];
    const int*   nbr_k = (const int*)d_in[11];
    float* out = (float*)d_out;

    cudaFuncSetAttribute(cfconv_mma,
                         cudaFuncAttributeMaxDynamicSharedMemorySize,
                         SMEM_BYTES);

    y_kernel<<<B_ * A_, 128>>>(x, Win);
    cfconv_mma<<<B_ * A_, 512, SMEM_BYTES>>>(
        r_ij, mask, Wf1, bf1, Wf2, bf2, Wout, bout, nbr_j, nbr_k, out);
}

// round 5
// speedup vs baseline: 3.3901x; 1.1905x over previous
#include <cuda_runtime.h>
#include <cstdint>

#define B_   2
#define A_   512
#define T_   512
#define F_   128
#define RBF_ 25
#define TBLK 128
#define NBLK (T_/TBLK)

// Precomputed y = x @ Win, [B,A,F]
__device__ __align__(16) float g_y[B_ * A_ * F_];

// ---------------- smem layout (float offsets) ----------------
#define OFF_WF1 0               // [32][136] tf32      4352
#define OFF_RS  4352            // [128][36] tf32      4608
#define OFF_H1  8960            // [128][136] tf32     17408 (stride 136: B-frag conflict-free)
#define OFF_GT  26368           // [128][132] tf32     16896 (stride 132: A-frag conflict-free; reused: Wf2)
#define OFF_BF1 43264           // 128
#define OFF_NJ  43392           // 128 int
#define OFF_NK  43520           // 128 int
#define OFF_MSK 43648           // 128
#define OFF_GS  43776           // 256
#define OFF_PRT 44032           // 4*128
#define OFF_ACC 44544           // 128
#define SMEM_FLOATS 44672
#define SMEM_BYTES  (SMEM_FLOATS * 4)

#define LN2 0.69314718055994530942f

// fast shifted softplus: 2 MUFU + few FFMA; abs err ~1e-6 (<< tf32 noise)
static __device__ __forceinline__ float ssp(float v) {
    float e = __expf(-fabsf(v));
    return fmaxf(v, 0.0f) + LN2 * __log2f(1.0f + e) - LN2;
}
static __device__ __forceinline__ uint32_t f2t(float f) {
    uint32_t r;
    asm("cvt.rna.tf32.f32 %0, %1;" : "=r"(r) : "f"(f));
    return r;
}
static __device__ __forceinline__ void mma8(float* d, const uint32_t* a,
                                            const uint32_t* b) {
    asm volatile(
        "mma.sync.aligned.m16n8k8.row.col.f32.tf32.tf32.f32 "
        "{%0,%1,%2,%3}, {%4,%5,%6,%7}, {%8,%9}, {%0,%1,%2,%3};"
        : "+f"(d[0]), "+f"(d[1]), "+f"(d[2]), "+f"(d[3])
        : "r"(a[0]), "r"(a[1]), "r"(a[2]), "r"(a[3]),
          "r"(b[0]), "r"(b[1]));
}

// ---------------------------------------------------------------------------
// Kernel 1: y[ba,f] = sum_i x[ba,i] * Win[i,f]
// ---------------------------------------------------------------------------
__global__ __launch_bounds__(128) void y_kernel(const float* __restrict__ x,
                                                const float* __restrict__ Win) {
    int ba = blockIdx.x, f = threadIdx.x;
    __shared__ float xs[F_];
    xs[f] = x[ba * F_ + f];
    __syncthreads();
    float acc = 0.0f;
#pragma unroll 8
    for (int i = 0; i < F_; i++) acc = fmaf(xs[i], Win[i * F_ + f], acc);
    g_y[ba * F_ + f] = acc;
}

// ---------------------------------------------------------------------------
// Main fused kernel. One CTA per (b,a). 512 threads = 16 warps.
// ---------------------------------------------------------------------------
__global__ __launch_bounds__(512, 1) void cfconv_mma(
    const float* __restrict__ r_ij,
    const float* __restrict__ mask,
    const float* __restrict__ Wf1,
    const float* __restrict__ bf1,
    const float* __restrict__ Wf2,
    const float* __restrict__ bf2,
    const float* __restrict__ Wout,
    const float* __restrict__ bout,
    const int*   __restrict__ nbr_j,
    const int*   __restrict__ nbr_k,
    float*       __restrict__ out)
{
    extern __shared__ float sm[];
    uint32_t* smu = (uint32_t*)sm;

    const int tid  = threadIdx.x;
    const int wid  = tid >> 5;
    const int lane = tid & 31;
    const int gr   = lane >> 2;
    const int t4   = lane & 3;
    const int ba   = blockIdx.x;
    const int b    = ba / A_;

    // ---- one-time loads ----
    for (int i = tid; i < 32 * F_; i += 512) {
        int k = i >> 7, g = i & 127;
        float v = (k < RBF_) ? Wf1[k * F_ + g] : 0.0f;
        smu[OFF_WF1 + k * 136 + g] = f2t(v);
    }
    if (tid < 128) sm[OFF_BF1 + tid] = bf1[tid];
    __syncthreads();

    // stage-2 accumulator: warp (wm,wn) owns f-rows [wm*32,+32), g-cols [wn*32,+32)
    const int wm = wid & 3, wn = wid >> 2;
    const int m0 = wm * 32, n0 = wn * 32;
    float P[2][4][4];
#pragma unroll
    for (int mt = 0; mt < 2; mt++)
#pragma unroll
        for (int nt = 0; nt < 4; nt++)
#pragma unroll
            for (int j = 0; j < 4; j++) P[mt][nt][j] = 0.0f;

    // precompute stage-2 fragment base pointers (immediate offsets per k after unroll)
    const uint32_t* gA0 = &smu[OFF_GT + (m0 + gr) * 132 + t4];        // row r0
    const uint32_t* gA1 = &smu[OFF_GT + (m0 + gr + 8) * 132 + t4];    // row r0+8
    const uint32_t* gA2 = &smu[OFF_GT + (m0 + 16 + gr) * 132 + t4];   // mt=1
    const uint32_t* gA3 = &smu[OFF_GT + (m0 + 24 + gr) * 132 + t4];
    const uint32_t* hB  = &smu[OFF_H1 + t4 * 136 + n0 + gr];          // + kk*136 [+4*136]

    float gsum = 0.0f;

    for (int blk = 0; blk < NBLK; blk++) {
        const uint32_t t0g = (uint32_t)ba * T_ + blk * TBLK;

        if (tid < 256) {
            // ===== warps 0-7: load R block [128t][32r] tf32 =====
#pragma unroll
            for (int i2 = 0; i2 < 16; i2++) {
                uint32_t i = tid + i2 * 256;
                uint32_t t = i >> 5, r = i & 31;
                float v = (r < RBF_) ? r_ij[(t0g + t) * RBF_ + r] : 0.0f;
                smu[OFF_RS + t * 36 + r] = f2t(v);
            }
            asm volatile("bar.sync 1, 256;" ::: "memory");

            // ===== stage 1: H1 = ssp(R @ Wf1 + bf1) =====
            const int tb = wid * 16;
            const uint32_t* rA = &smu[OFF_RS + (tb + gr) * 36 + t4];
            const uint32_t* rB = &smu[OFF_RS + (tb + gr + 8) * 36 + t4];
#pragma unroll
            for (int half = 0; half < 2; half++) {
                const int nb = half * 64;
                const uint32_t* wB = &smu[OFF_WF1 + t4 * 136 + nb + gr];
                float s1[8][4];
#pragma unroll
                for (int nt = 0; nt < 8; nt++)
#pragma unroll
                    for (int j = 0; j < 4; j++) s1[nt][j] = 0.0f;

#pragma unroll
                for (int k = 0; k < 4; k++) {
                    const int kk = k * 8;
                    uint32_t a[4];
                    a[0] = rA[kk];
                    a[1] = rB[kk];
                    a[2] = rA[kk + 4];
                    a[3] = rB[kk + 4];
#pragma unroll
                    for (int nt = 0; nt < 8; nt++) {
                        uint32_t bfr[2];
                        bfr[0] = wB[kk * 136 + nt * 8];
                        bfr[1] = wB[(kk + 4) * 136 + nt * 8];
                        mma8(s1[nt], a, bfr);
                    }
                }
#pragma unroll
                for (int nt = 0; nt < 8; nt++) {
                    int c = nb + nt * 8 + 2 * t4;
                    float bc0 = sm[OFF_BF1 + c];
                    float bc1 = sm[OFF_BF1 + c + 1];
                    smu[OFF_H1 + (tb + gr) * 136 + c]     = f2t(ssp(s1[nt][0] + bc0));
                    smu[OFF_H1 + (tb + gr) * 136 + c + 1] = f2t(ssp(s1[nt][1] + bc1));
                    smu[OFF_H1 + (tb + gr + 8) * 136 + c]     = f2t(ssp(s1[nt][2] + bc0));
                    smu[OFF_H1 + (tb + gr + 8) * 136 + c + 1] = f2t(ssp(s1[nt][3] + bc1));
                }
            }
        } else {
            // ===== warps 8-15: gather G^T[f][t] =====
            const int idx = tid - 256;
            const uint32_t f = idx & 127;
            const int th = idx >> 7;
            if (idx < 128) {
                ((int*)(sm + OFF_NJ))[idx] = nbr_j[t0g + idx];
                ((int*)(sm + OFF_NK))[idx] = nbr_k[t0g + idx];
                sm[OFF_MSK + idx]          = mask[t0g + idx];
            }
            asm volatile("bar.sync 2, 256;" ::: "memory");

            const float* yb  = g_y + (uint32_t)b * (A_ * F_) + f;
            const int*   sNj = (const int*)(sm + OFF_NJ);
            const int*   sNk = (const int*)(sm + OFF_NK);
            const float* sM  = sm + OFF_MSK;

            const int tbeg = th * 64;
#pragma unroll 2
            for (int tt = tbeg; tt < tbeg + 64; tt += 4) {
                uint4 gq;
                uint32_t* gp = (uint32_t*)&gq;
#pragma unroll
                for (int w = 0; w < 4; w++) {
                    int t = tt + w;
                    float gv = yb[(uint32_t)sNj[t] * F_]
                             * yb[(uint32_t)sNk[t] * F_] * sM[t];
                    gsum += gv;
                    gp[w] = f2t(gv);
                }
                *(uint4*)&smu[OFF_GT + f * 132 + tt] = gq;
            }
        }
        __syncthreads();

        // ===== stage 2: P += G^T @ H1 (K=128), fully unrolled =====
#pragma unroll
        for (int k = 0; k < 16; k++) {
            const int kk = k * 8;
            uint32_t a[2][4];
            a[0][0] = gA0[kk];
            a[0][1] = gA1[kk];
            a[0][2] = gA0[kk + 4];
            a[0][3] = gA1[kk + 4];
            a[1][0] = gA2[kk];
            a[1][1] = gA3[kk];
            a[1][2] = gA2[kk + 4];
            a[1][3] = gA3[kk + 4];
#pragma unroll
            for (int nt = 0; nt < 4; nt++) {
                uint32_t bfr[2];
                bfr[0] = hB[kk * 136 + nt * 8];
                bfr[1] = hB[(kk + 4) * 136 + nt * 8];
                mma8(P[0][nt], a[0], bfr);
                mma8(P[1][nt], a[1], bfr);
            }
        }
        __syncthreads();
    }

    // ---- epilogue ----
    if (tid >= 256) sm[OFF_GS + tid - 256] = gsum;
    for (int i = tid; i < F_ * F_; i += 512) sm[OFF_GT + i] = Wf2[i];
    __syncthreads();

#pragma unroll
    for (int mt = 0; mt < 2; mt++) {
        int f0 = m0 + mt * 16 + gr;
        int f1 = f0 + 8;
        float p0 = 0.0f, p1 = 0.0f;
#pragma unroll
        for (int nt = 0; nt < 4; nt++) {
            int c = n0 + nt * 8 + 2 * t4;
            p0 += P[mt][nt][0] * sm[OFF_GT + c * F_ + f0]
                + P[mt][nt][1] * sm[OFF_GT + (c + 1) * F_ + f0];
            p1 += P[mt][nt][2] * sm[OFF_GT + c * F_ + f1]
                + P[mt][nt][3] * sm[OFF_GT + (c + 1) * F_ + f1];
        }
        p0 += __shfl_xor_sync(0xFFFFFFFFu, p0, 1);
        p0 += __shfl_xor_sync(0xFFFFFFFFu, p0, 2);
        p1 += __shfl_xor_sync(0xFFFFFFFFu, p1, 1);
        p1 += __shfl_xor_sync(0xFFFFFFFFu, p1, 2);
        if (t4 == 0) {
            sm[OFF_PRT + wn * F_ + f0] = p0;
            sm[OFF_PRT + wn * F_ + f1] = p1;
        }
    }
    __syncthreads();

    if (tid < 128) {
        float acc = sm[OFF_PRT + tid]          + sm[OFF_PRT + F_ + tid]
                  + sm[OFF_PRT + 2 * F_ + tid] + sm[OFF_PRT + 3 * F_ + tid]
                  + bf2[tid] * (sm[OFF_GS + tid] + sm[OFF_GS + tid + 128]);
        sm[OFF_ACC + tid] = acc;
    }
    __syncthreads();

    if (tid < 128) {
        float o = bout[tid];
#pragma unroll 8
        for (int g = 0; g < F_; g++)
            o = fmaf(sm[OFF_ACC + g], Wout[g * F_ + tid], o);
        out[(uint32_t)ba * F_ + tid] = ssp(o);
    }
}

// ---------------------------------------------------------------------------
extern "C" void kernel_launch(void* const* d_in, const int* in_sizes, int n_in,
                              void* d_out, int out_size)
{
    const float* x     = (const float*)d_in[0];
    const float* r_ij  = (const float*)d_in[1];
    const float* mask  = (const float*)d_in[2];
    const float* Wf1   = (const float*)d_in[3];
    const float* bf1   = (const float*)d_in[4];
    const float* Wf2   = (const float*)d_in[5];
    const float* bf2   = (const float*)d_in[6];
    const float* Win   = (const float*)d_in[7];
    const float* Wout  = (const float*)d_in[8];
    const float* bout  = (const float*)d_in[9];
    const int*   nbr_j = (const int*)d_in[10];
    const int*   nbr_k = (const int*)d_in[11];
    float* out = (float*)d_out;

    cudaFuncSetAttribute(cfconv_mma,
                         cudaFuncAttributeMaxDynamicSharedMemorySize,
                         SMEM_BYTES);

    y_kernel<<<B_ * A_, 128>>>(x, Win);
    cfconv_mma<<<B_ * A_, 512, SMEM_BYTES>>>(
        r_ij, mask, Wf1, bf1, Wf2, bf2, Wout, bout, nbr_j, nbr_k, out);
}